// round 6
// baseline (speedup 1.0000x reference)
#include <cuda_runtime.h>
#include <cuda_bf16.h>
#include <cstdint>

#define NN   50000
#define FIN  256
#define HH   4
#define CC   32
#define HC   128
#define EMAX 1600000

// ---------------- scratch (static __device__, no allocations) ----------------
__device__ float    g_xd[(size_t)NN * FIN];        // dropped-out x   (51.2 MB)
__device__ float    g_h [(size_t)NN * HC];         // x @ W           (25.6 MB)
__device__ float    g_as[NN * HH];                 // <h, att_src>
__device__ float    g_ad[NN * HH];                 // <h, att_dst>
__device__ unsigned g_mbits[NN * HH];              // segment max (orderable bits)
__device__ float    g_den[NN * HH];                // softmax denominator
__device__ float    g_ee[(size_t)(EMAX + NN) * HH];// exp(e - m[dst]) per edge/head

// ---------------- helpers ----------------
__device__ __forceinline__ unsigned f2ord(float f) {
    unsigned u = __float_as_uint(f);
    return (u & 0x80000000u) ? ~u : (u | 0x80000000u);
}
__device__ __forceinline__ float ord2f(unsigned u) {
    unsigned b = (u & 0x80000000u) ? (u & 0x7FFFFFFFu) : ~u;
    return __uint_as_float(b);
}
__device__ __forceinline__ void red_add_v4(float* p, float a, float b, float c, float d) {
    asm volatile("red.global.add.v4.f32 [%0], {%1,%2,%3,%4};"
                 :: "l"(p), "f"(a), "f"(b), "f"(c), "f"(d) : "memory");
}

// ---------------- kernel 0: zero accumulators ----------------
__global__ void k_init(float* out, int n_out, int nh) {
    int i = blockIdx.x * blockDim.x + threadIdx.x;
    if (i < n_out) out[i] = 0.0f;
    if (i < nh) { g_den[i] = 0.0f; g_mbits[i] = 0u; }
}

// ---------------- kernel 1: JAX threefry dropout (partitionable, XOR combine)
// per element i: (b1,b2) = threefry2x32(key=(0,1), x0 = hi(i) = 0, x1 = lo(i) = i)
// 32-bit random bits = b1 ^ b2   (JAX partitionable path, bit_width==32)
// u = bitcast((bits>>9)|0x3f800000) - 1;  keep = u < 0.8
__global__ void k_dropout(const float* __restrict__ x, int total) {
    int i = blockIdx.x * blockDim.x + threadIdx.x;
    if (i >= total) return;

    unsigned x0 = 0u;              // high word of 64-bit counter (i < 2^32)
    unsigned x1 = (unsigned)i;     // low word
    const unsigned ks0 = 0u, ks1 = 1u, ks2 = 0x1BD11BDBu; // 0x1BD11BDA ^ 0 ^ 1
    x0 += ks0; x1 += ks1;

#define TF_R(r) { x0 += x1; x1 = (x1 << (r)) | (x1 >> (32 - (r))); x1 ^= x0; }
    TF_R(13) TF_R(15) TF_R(26) TF_R(6)   x0 += ks1; x1 += ks2 + 1u;
    TF_R(17) TF_R(29) TF_R(16) TF_R(24)  x0 += ks2; x1 += ks0 + 2u;
    TF_R(13) TF_R(15) TF_R(26) TF_R(6)   x0 += ks0; x1 += ks1 + 3u;
    TF_R(17) TF_R(29) TF_R(16) TF_R(24)  x0 += ks1; x1 += ks2 + 4u;
    TF_R(13) TF_R(15) TF_R(26) TF_R(6)   x0 += ks2; x1 += ks0 + 5u;
#undef TF_R

    unsigned bits = x0 ^ x1;       // XOR of both output lanes
    float u = __uint_as_float((bits >> 9) | 0x3F800000u) - 1.0f;
    g_xd[i] = (u < 0.8f) ? x[i] * 1.25f : 0.0f;
}

// ---------------- kernel 2: tiled SGEMM  h = xd @ W  (M x 256 @ 256 x 128) ----
__global__ void k_gemm(const float* __restrict__ W, int M) {
    __shared__ float As[16][128];
    __shared__ float Bs[16][128];
    const int bm  = blockIdx.x * 128;
    const int tid = threadIdx.x;

    const int arow = tid >> 2;          // 0..63
    const int acol = (tid & 3) << 2;    // 0,4,8,12
    const int brow = tid >> 5;          // 0..7
    const int bcol = (tid & 31) << 2;   // 0..124

    const int tx = (tid & 15) << 3;     // out col base
    const int ty = (tid >> 4) << 3;     // out row base (within tile)

    float acc[8][8];
#pragma unroll
    for (int i = 0; i < 8; i++)
#pragma unroll
        for (int j = 0; j < 8; j++) acc[i][j] = 0.0f;

    for (int kt = 0; kt < 256; kt += 16) {
#pragma unroll
        for (int r = 0; r < 2; r++) {
            int row = bm + arow + r * 64;
            float4 v = make_float4(0.f, 0.f, 0.f, 0.f);
            if (row < M) v = *(const float4*)&g_xd[(size_t)row * 256 + kt + acol];
            As[acol + 0][arow + r * 64] = v.x;
            As[acol + 1][arow + r * 64] = v.y;
            As[acol + 2][arow + r * 64] = v.z;
            As[acol + 3][arow + r * 64] = v.w;
        }
#pragma unroll
        for (int r = 0; r < 2; r++) {
            *(float4*)&Bs[brow + r * 8][bcol] =
                *(const float4*)&W[(size_t)(kt + brow + r * 8) * 128 + bcol];
        }
        __syncthreads();

#pragma unroll
        for (int k = 0; k < 16; k++) {
            float4 a0 = *(float4*)&As[k][ty];
            float4 a1 = *(float4*)&As[k][ty + 4];
            float4 b0 = *(float4*)&Bs[k][tx];
            float4 b1 = *(float4*)&Bs[k][tx + 4];
            float ar[8] = {a0.x, a0.y, a0.z, a0.w, a1.x, a1.y, a1.z, a1.w};
            float br[8] = {b0.x, b0.y, b0.z, b0.w, b1.x, b1.y, b1.z, b1.w};
#pragma unroll
            for (int i = 0; i < 8; i++)
#pragma unroll
                for (int j = 0; j < 8; j++) acc[i][j] += ar[i] * br[j];
        }
        __syncthreads();
    }

#pragma unroll
    for (int i = 0; i < 8; i++) {
        int row = bm + ty + i;
        if (row < M) {
            *(float4*)&g_h[(size_t)row * 128 + tx]     = make_float4(acc[i][0], acc[i][1], acc[i][2], acc[i][3]);
            *(float4*)&g_h[(size_t)row * 128 + tx + 4] = make_float4(acc[i][4], acc[i][5], acc[i][6], acc[i][7]);
        }
    }
}

// ---------------- kernel 3: per-(node,head) attention logits ----------------
__global__ void k_att(const float* __restrict__ att_src,
                      const float* __restrict__ att_dst, int n) {
    int i = blockIdx.x * blockDim.x + threadIdx.x;
    if (i >= n * HH) return;
    int h = i & 3;
    int node = i >> 2;
    const float* hp = &g_h[(size_t)node * HC + h * CC];
    float s = 0.f, d = 0.f;
#pragma unroll
    for (int c = 0; c < CC; c++) {
        float v = hp[c];
        s += v * att_src[h * CC + c];
        d += v * att_dst[h * CC + c];
    }
    g_as[i] = s;
    g_ad[i] = d;
}

// ---------------- kernel 4: segment max over incoming edges ----------------
__global__ void k_emax(const int* __restrict__ ei, int E, int n) {
    int e = blockIdx.x * blockDim.x + threadIdx.x;
    if (e >= E + n) return;
    int s, d;
    if (e < E) { s = ei[e]; d = ei[E + e]; }
    else       { s = d = e - E; }
    float4 as = *(const float4*)&g_as[s * 4];
    float4 ad = *(const float4*)&g_ad[d * 4];
    float ev[4] = {as.x + ad.x, as.y + ad.y, as.z + ad.z, as.w + ad.w};
#pragma unroll
    for (int h = 0; h < 4; h++) {
        float f = ev[h] >= 0.f ? ev[h] : 0.2f * ev[h];
        atomicMax(&g_mbits[d * 4 + h], f2ord(f));
    }
}

// ---------------- kernel 5: exp + denominator ----------------
__global__ void k_esum(const int* __restrict__ ei, int E, int n) {
    int e = blockIdx.x * blockDim.x + threadIdx.x;
    if (e >= E + n) return;
    int s, d;
    if (e < E) { s = ei[e]; d = ei[E + e]; }
    else       { s = d = e - E; }
    float4 as = *(const float4*)&g_as[s * 4];
    float4 ad = *(const float4*)&g_ad[d * 4];
    uint4 mb = *(const uint4*)&g_mbits[d * 4];
    float m[4] = {ord2f(mb.x), ord2f(mb.y), ord2f(mb.z), ord2f(mb.w)};
    float ev[4] = {as.x + ad.x, as.y + ad.y, as.z + ad.z, as.w + ad.w};
    float ee[4];
#pragma unroll
    for (int h = 0; h < 4; h++) {
        float f = ev[h] >= 0.f ? ev[h] : 0.2f * ev[h];
        ee[h] = expf(f - m[h]);
        atomicAdd(&g_den[d * 4 + h], ee[h]);
    }
    *(float4*)&g_ee[(size_t)e * 4] = make_float4(ee[0], ee[1], ee[2], ee[3]);
}

// ---------------- kernel 6: weighted scatter-aggregate (warp per edge) ------
__global__ void k_agg(const int* __restrict__ ei, int E, int n,
                      float* __restrict__ out) {
    int gid = blockIdx.x * blockDim.x + threadIdx.x;
    int e = gid >> 5;
    int lane = gid & 31;
    if (e >= E + n) return;
    int s, d;
    if (e < E) { s = ei[e]; d = ei[E + e]; }
    else       { s = d = e - E; }
    int head = lane >> 3;                      // 8 lanes per head (32 floats)
    float w = g_ee[(size_t)e * 4 + head];
    float4 hv = *(const float4*)&g_h[(size_t)s * HC + lane * 4];
    float* dst = &out[(size_t)d * HC + lane * 4];
    red_add_v4(dst, hv.x * w, hv.y * w, hv.z * w, hv.w * w);
}

// ---------------- kernel 7: divide, bias, PReLU (in place) ----------------
__global__ void k_final(float* __restrict__ out, const float* __restrict__ bias,
                        const float* __restrict__ prelu_a, int n) {
    int i = blockIdx.x * blockDim.x + threadIdx.x;
    if (i >= n * HC) return;
    int node = i >> 7;
    int j = i & 127;
    int h = j >> 5;
    float den = g_den[node * 4 + h];
    float v = out[i] / fmaxf(den, 1e-16f) + bias[j];
    float a = *prelu_a;
    out[i] = v >= 0.f ? v : a * v;
}

// ---------------- launch ----------------
extern "C" void kernel_launch(void* const* d_in, const int* in_sizes, int n_in,
                              void* d_out, int out_size) {
    const float* x        = (const float*)d_in[0];
    const float* W        = (const float*)d_in[1];
    const float* att_src  = (const float*)d_in[2];
    const float* att_dst  = (const float*)d_in[3];
    const float* bias     = (const float*)d_in[4];
    const float* prelu_a  = (const float*)d_in[5];
    const int*   ei       = (const int*)d_in[6];   // JAX default: int32 (x64 disabled)

    const int n     = in_sizes[0] / FIN;   // 50000
    const int E     = in_sizes[6] / 2;     // 1600000
    const int total = n * FIN;
    const int ET    = E + n;
    float* out = (float*)d_out;

    k_init   <<<(n * HC + 511) / 512, 512>>>(out, n * HC, n * HH);
    k_dropout<<<(total + 255) / 256, 256>>>(x, total);
    k_gemm   <<<(n + 127) / 128, 256>>>(W, n);
    k_att    <<<(n * HH + 255) / 256, 256>>>(att_src, att_dst, n);
    k_emax   <<<(ET + 255) / 256, 256>>>(ei, E, n);
    k_esum   <<<(ET + 255) / 256, 256>>>(ei, E, n);
    k_agg    <<<((long long)ET * 32 + 255) / 256, 256>>>(ei, E, n, out);
    k_final  <<<(n * HC + 255) / 256, 256>>>(out, bias, prelu_a, n);
}

// round 7
// speedup vs baseline: 1.0759x; 1.0759x over previous
#include <cuda_runtime.h>
#include <cuda_bf16.h>
#include <cstdint>

#define NN   50000
#define FIN  256
#define HH   4
#define CC   32
#define HC   128
#define EMAX 1600000

// ---------------- scratch (static __device__, no allocations) ----------------
__device__ float    g_h [(size_t)NN * HC];         // dropout(x) @ W  (25.6 MB)
__device__ float    g_as[NN * HH];                 // <h, att_src>
__device__ float    g_ad[NN * HH];                 // <h, att_dst>
__device__ unsigned g_mbits[NN * HH];              // segment max (orderable bits)
__device__ float    g_den[NN * HH];                // softmax denominator
__device__ float    g_ee[(size_t)(EMAX + NN) * HH];// logits, then exp(e-m) per edge/head

// ---------------- helpers ----------------
__device__ __forceinline__ unsigned f2ord(float f) {
    unsigned u = __float_as_uint(f);
    return (u & 0x80000000u) ? ~u : (u | 0x80000000u);
}
__device__ __forceinline__ float ord2f(unsigned u) {
    unsigned b = (u & 0x80000000u) ? (u & 0x7FFFFFFFu) : ~u;
    return __uint_as_float(b);
}
__device__ __forceinline__ void red_add_v4(float* p, float a, float b, float c, float d) {
    asm volatile("red.global.add.v4.f32 [%0], {%1,%2,%3,%4};"
                 :: "l"(p), "f"(a), "f"(b), "f"(c), "f"(d) : "memory");
}

// JAX partitionable threefry dropout factor for element index i:
// (b1,b2) = threefry2x32(key=(0,1), x0=0, x1=i); bits = b1^b2
// keep if bitcast((bits>>9)|0x3f800000)-1 < 0.8  ->  * 1.25, else 0
__device__ __forceinline__ float drop_factor(unsigned i) {
    unsigned x0 = 0u, x1 = i;
    const unsigned ks0 = 0u, ks1 = 1u, ks2 = 0x1BD11BDBu;
    x0 += ks0; x1 += ks1;
#define TF_R(r) { x0 += x1; x1 = (x1 << (r)) | (x1 >> (32 - (r))); x1 ^= x0; }
    TF_R(13) TF_R(15) TF_R(26) TF_R(6)   x0 += ks1; x1 += ks2 + 1u;
    TF_R(17) TF_R(29) TF_R(16) TF_R(24)  x0 += ks2; x1 += ks0 + 2u;
    TF_R(13) TF_R(15) TF_R(26) TF_R(6)   x0 += ks0; x1 += ks1 + 3u;
    TF_R(17) TF_R(29) TF_R(16) TF_R(24)  x0 += ks1; x1 += ks2 + 4u;
    TF_R(13) TF_R(15) TF_R(26) TF_R(6)   x0 += ks2; x1 += ks0 + 5u;
#undef TF_R
    unsigned bits = x0 ^ x1;
    float u = __uint_as_float((bits >> 9) | 0x3F800000u) - 1.0f;
    return (u < 0.8f) ? 1.25f : 0.0f;
}

// ---------------- kernel 0: zero accumulators ----------------
__global__ void k_init(float* out, int n_out, int nh) {
    int i = blockIdx.x * blockDim.x + threadIdx.x;
    if (i < n_out) out[i] = 0.0f;
    if (i < nh) { g_den[i] = 0.0f; g_mbits[i] = 0u; }
}

// ---------------- kernel 1: SGEMM with fused threefry dropout on A ----------
// h = dropout(x) @ W   (M x 256 @ 256 x 128)
__global__ void k_gemm(const float* __restrict__ X, const float* __restrict__ W, int M) {
    __shared__ float As[16][128];
    __shared__ float Bs[16][128];
    const int bm  = blockIdx.x * 128;
    const int tid = threadIdx.x;

    const int arow = tid >> 2;          // 0..63
    const int acol = (tid & 3) << 2;    // 0,4,8,12
    const int brow = tid >> 5;          // 0..7
    const int bcol = (tid & 31) << 2;   // 0..124

    const int tx = (tid & 15) << 3;     // out col base
    const int ty = (tid >> 4) << 3;     // out row base (within tile)

    float acc[8][8];
#pragma unroll
    for (int i = 0; i < 8; i++)
#pragma unroll
        for (int j = 0; j < 8; j++) acc[i][j] = 0.0f;

    for (int kt = 0; kt < 256; kt += 16) {
#pragma unroll
        for (int r = 0; r < 2; r++) {
            int row = bm + arow + r * 64;
            float4 v = make_float4(0.f, 0.f, 0.f, 0.f);
            if (row < M) {
                unsigned base = (unsigned)row * 256u + (unsigned)(kt + acol);
                v = *(const float4*)&X[(size_t)row * 256 + kt + acol];
                v.x *= drop_factor(base + 0u);
                v.y *= drop_factor(base + 1u);
                v.z *= drop_factor(base + 2u);
                v.w *= drop_factor(base + 3u);
            }
            As[acol + 0][arow + r * 64] = v.x;
            As[acol + 1][arow + r * 64] = v.y;
            As[acol + 2][arow + r * 64] = v.z;
            As[acol + 3][arow + r * 64] = v.w;
        }
#pragma unroll
        for (int r = 0; r < 2; r++) {
            *(float4*)&Bs[brow + r * 8][bcol] =
                *(const float4*)&W[(size_t)(kt + brow + r * 8) * 128 + bcol];
        }
        __syncthreads();

#pragma unroll
        for (int k = 0; k < 16; k++) {
            float4 a0 = *(float4*)&As[k][ty];
            float4 a1 = *(float4*)&As[k][ty + 4];
            float4 b0 = *(float4*)&Bs[k][tx];
            float4 b1 = *(float4*)&Bs[k][tx + 4];
            float ar[8] = {a0.x, a0.y, a0.z, a0.w, a1.x, a1.y, a1.z, a1.w};
            float br[8] = {b0.x, b0.y, b0.z, b0.w, b1.x, b1.y, b1.z, b1.w};
#pragma unroll
            for (int i = 0; i < 8; i++)
#pragma unroll
                for (int j = 0; j < 8; j++) acc[i][j] += ar[i] * br[j];
        }
        __syncthreads();
    }

#pragma unroll
    for (int i = 0; i < 8; i++) {
        int row = bm + ty + i;
        if (row < M) {
            *(float4*)&g_h[(size_t)row * 128 + tx]     = make_float4(acc[i][0], acc[i][1], acc[i][2], acc[i][3]);
            *(float4*)&g_h[(size_t)row * 128 + tx + 4] = make_float4(acc[i][4], acc[i][5], acc[i][6], acc[i][7]);
        }
    }
}

// ---------------- kernel 2: attention logits, warp per node (coalesced) -----
__global__ void k_att(const float* __restrict__ att_src,
                      const float* __restrict__ att_dst, int n) {
    int gid  = blockIdx.x * blockDim.x + threadIdx.x;
    int node = gid >> 5;
    int lane = gid & 31;
    if (node >= n) return;

    float4 hv = *(const float4*)&g_h[(size_t)node * HC + lane * 4];
    float4 vs = *(const float4*)&att_src[lane * 4];   // [H*C] flat, col = lane*4
    float4 vd = *(const float4*)&att_dst[lane * 4];
    float s = hv.x * vs.x + hv.y * vs.y + hv.z * vs.z + hv.w * vs.w;
    float d = hv.x * vd.x + hv.y * vd.y + hv.z * vd.z + hv.w * vd.w;

    // reduce within each 8-lane head group
#pragma unroll
    for (int off = 4; off >= 1; off >>= 1) {
        s += __shfl_xor_sync(0xFFFFFFFFu, s, off);
        d += __shfl_xor_sync(0xFFFFFFFFu, d, off);
    }
    if ((lane & 7) == 0) {
        int h = lane >> 3;
        g_as[node * 4 + h] = s;
        g_ad[node * 4 + h] = d;
    }
}

// ---------------- kernel 3: logits + segment max; stores ev into g_ee -------
__global__ void k_emax(const int* __restrict__ ei, int E, int n) {
    int e = blockIdx.x * blockDim.x + threadIdx.x;
    if (e >= E + n) return;
    int s, d;
    if (e < E) { s = ei[e]; d = ei[E + e]; }
    else       { s = d = e - E; }
    float4 as = *(const float4*)&g_as[s * 4];
    float4 ad = *(const float4*)&g_ad[d * 4];
    float ev[4] = {as.x + ad.x, as.y + ad.y, as.z + ad.z, as.w + ad.w};
#pragma unroll
    for (int h = 0; h < 4; h++) {
        ev[h] = ev[h] >= 0.f ? ev[h] : 0.2f * ev[h];
        atomicMax(&g_mbits[d * 4 + h], f2ord(ev[h]));
    }
    *(float4*)&g_ee[(size_t)e * 4] = make_float4(ev[0], ev[1], ev[2], ev[3]);
}

// ---------------- kernel 4: exp + denominator (reads stored ev) -------------
__global__ void k_esum(const int* __restrict__ ei, int E, int n) {
    int e = blockIdx.x * blockDim.x + threadIdx.x;
    if (e >= E + n) return;
    int d = (e < E) ? ei[E + e] : e - E;
    float4 evv = *(const float4*)&g_ee[(size_t)e * 4];
    uint4 mb = *(const uint4*)&g_mbits[d * 4];
    float m[4] = {ord2f(mb.x), ord2f(mb.y), ord2f(mb.z), ord2f(mb.w)};
    float ev[4] = {evv.x, evv.y, evv.z, evv.w};
    float ee[4];
#pragma unroll
    for (int h = 0; h < 4; h++) {
        ee[h] = expf(ev[h] - m[h]);
        atomicAdd(&g_den[d * 4 + h], ee[h]);
    }
    *(float4*)&g_ee[(size_t)e * 4] = make_float4(ee[0], ee[1], ee[2], ee[3]);
}

// ---------------- kernel 5: weighted scatter-aggregate (warp per edge) ------
__global__ void k_agg(const int* __restrict__ ei, int E, int n,
                      float* __restrict__ out) {
    int gid = blockIdx.x * blockDim.x + threadIdx.x;
    int e = gid >> 5;
    int lane = gid & 31;
    if (e >= E + n) return;
    int s, d;
    if (e < E) { s = ei[e]; d = ei[E + e]; }
    else       { s = d = e - E; }
    int head = lane >> 3;                      // 8 lanes per head (32 floats)
    float w = g_ee[(size_t)e * 4 + head];
    float4 hv = *(const float4*)&g_h[(size_t)s * HC + lane * 4];
    float* dst = &out[(size_t)d * HC + lane * 4];
    red_add_v4(dst, hv.x * w, hv.y * w, hv.z * w, hv.w * w);
}

// ---------------- kernel 6: divide, bias, PReLU (in place) ----------------
__global__ void k_final(float* __restrict__ out, const float* __restrict__ bias,
                        const float* __restrict__ prelu_a, int n) {
    int i = blockIdx.x * blockDim.x + threadIdx.x;
    if (i >= n * HC) return;
    int node = i >> 7;
    int j = i & 127;
    int h = j >> 5;
    float den = g_den[node * 4 + h];
    float v = out[i] / fmaxf(den, 1e-16f) + bias[j];
    float a = *prelu_a;
    out[i] = v >= 0.f ? v : a * v;
}

// ---------------- launch ----------------
extern "C" void kernel_launch(void* const* d_in, const int* in_sizes, int n_in,
                              void* d_out, int out_size) {
    const float* x        = (const float*)d_in[0];
    const float* W        = (const float*)d_in[1];
    const float* att_src  = (const float*)d_in[2];
    const float* att_dst  = (const float*)d_in[3];
    const float* bias     = (const float*)d_in[4];
    const float* prelu_a  = (const float*)d_in[5];
    const int*   ei       = (const int*)d_in[6];   // int32 (JAX x64 disabled)

    const int n  = in_sizes[0] / FIN;   // 50000
    const int E  = in_sizes[6] / 2;     // 1600000
    const int ET = E + n;
    float* out = (float*)d_out;

    k_init  <<<(n * HC + 511) / 512, 512>>>(out, n * HC, n * HH);
    k_gemm  <<<(n + 127) / 128, 256>>>(x, W, n);
    k_att   <<<((long long)n * 32 + 255) / 256, 256>>>(att_src, att_dst, n);
    k_emax  <<<(ET + 255) / 256, 256>>>(ei, E, n);
    k_esum  <<<(ET + 255) / 256, 256>>>(ei, E, n);
    k_agg   <<<((long long)ET * 32 + 255) / 256, 256>>>(ei, E, n, out);
    k_final <<<(n * HC + 255) / 256, 256>>>(out, bias, prelu_a, n);
}

// round 8
// speedup vs baseline: 1.1935x; 1.1093x over previous
#include <cuda_runtime.h>
#include <cuda_bf16.h>
#include <cstdint>

#define NN   50000
#define FIN  256
#define HH   4
#define CC   32
#define HC   128
#define EMAX 1600000

// ---------------- scratch (static __device__, no allocations) ----------------
__device__ float g_h [(size_t)NN * HC];  // dropout(x) @ W  (25.6 MB)
__device__ float g_as[NN * HH];          // <h, att_src>
__device__ float g_ad[NN * HH];          // <h, att_dst>
__device__ float g_den[NN * HH];         // softmax denominator (no max-shift)

// ---------------- helpers ----------------
__device__ __forceinline__ void red_add_v4(float* p, float a, float b, float c, float d) {
    asm volatile("red.global.add.v4.f32 [%0], {%1,%2,%3,%4};"
                 :: "l"(p), "f"(a), "f"(b), "f"(c), "f"(d) : "memory");
}

// JAX partitionable threefry dropout factor for element index i:
// (b1,b2) = threefry2x32(key=(0,1), x0=0, x1=i); bits = b1^b2
// keep if bitcast((bits>>9)|0x3f800000)-1 < 0.8  ->  * 1.25, else 0
__device__ __forceinline__ float drop_factor(unsigned i) {
    unsigned x0 = 0u, x1 = i;
    const unsigned ks0 = 0u, ks1 = 1u, ks2 = 0x1BD11BDBu;
    x0 += ks0; x1 += ks1;
#define TF_R(r) { x0 += x1; x1 = (x1 << (r)) | (x1 >> (32 - (r))); x1 ^= x0; }
    TF_R(13) TF_R(15) TF_R(26) TF_R(6)   x0 += ks1; x1 += ks2 + 1u;
    TF_R(17) TF_R(29) TF_R(16) TF_R(24)  x0 += ks2; x1 += ks0 + 2u;
    TF_R(13) TF_R(15) TF_R(26) TF_R(6)   x0 += ks0; x1 += ks1 + 3u;
    TF_R(17) TF_R(29) TF_R(16) TF_R(24)  x0 += ks1; x1 += ks2 + 4u;
    TF_R(13) TF_R(15) TF_R(26) TF_R(6)   x0 += ks2; x1 += ks0 + 5u;
#undef TF_R
    unsigned bits = x0 ^ x1;
    float u = __uint_as_float((bits >> 9) | 0x3F800000u) - 1.0f;
    return (u < 0.8f) ? 1.25f : 0.0f;
}

// ---------------- kernel 0: zero accumulators ----------------
__global__ void k_init(float* out, int n_out, int nh) {
    int i = blockIdx.x * blockDim.x + threadIdx.x;
    if (i < n_out) out[i] = 0.0f;
    if (i < nh) g_den[i] = 0.0f;
}

// ---------------- kernel 1: SGEMM with fused threefry dropout on A ----------
// h = dropout(x) @ W   (M x 256 @ 256 x 128)
__global__ void k_gemm(const float* __restrict__ X, const float* __restrict__ W, int M) {
    __shared__ float As[16][128];
    __shared__ float Bs[16][128];
    const int bm  = blockIdx.x * 128;
    const int tid = threadIdx.x;

    const int arow = tid >> 2;          // 0..63
    const int acol = (tid & 3) << 2;    // 0,4,8,12
    const int brow = tid >> 5;          // 0..7
    const int bcol = (tid & 31) << 2;   // 0..124

    const int tx = (tid & 15) << 3;     // out col base
    const int ty = (tid >> 4) << 3;     // out row base (within tile)

    float acc[8][8];
#pragma unroll
    for (int i = 0; i < 8; i++)
#pragma unroll
        for (int j = 0; j < 8; j++) acc[i][j] = 0.0f;

    for (int kt = 0; kt < 256; kt += 16) {
#pragma unroll
        for (int r = 0; r < 2; r++) {
            int row = bm + arow + r * 64;
            float4 v = make_float4(0.f, 0.f, 0.f, 0.f);
            if (row < M) {
                unsigned base = (unsigned)row * 256u + (unsigned)(kt + acol);
                v = *(const float4*)&X[(size_t)row * 256 + kt + acol];
                v.x *= drop_factor(base + 0u);
                v.y *= drop_factor(base + 1u);
                v.z *= drop_factor(base + 2u);
                v.w *= drop_factor(base + 3u);
            }
            As[acol + 0][arow + r * 64] = v.x;
            As[acol + 1][arow + r * 64] = v.y;
            As[acol + 2][arow + r * 64] = v.z;
            As[acol + 3][arow + r * 64] = v.w;
        }
#pragma unroll
        for (int r = 0; r < 2; r++) {
            *(float4*)&Bs[brow + r * 8][bcol] =
                *(const float4*)&W[(size_t)(kt + brow + r * 8) * 128 + bcol];
        }
        __syncthreads();

#pragma unroll
        for (int k = 0; k < 16; k++) {
            float4 a0 = *(float4*)&As[k][ty];
            float4 a1 = *(float4*)&As[k][ty + 4];
            float4 b0 = *(float4*)&Bs[k][tx];
            float4 b1 = *(float4*)&Bs[k][tx + 4];
            float ar[8] = {a0.x, a0.y, a0.z, a0.w, a1.x, a1.y, a1.z, a1.w};
            float br[8] = {b0.x, b0.y, b0.z, b0.w, b1.x, b1.y, b1.z, b1.w};
#pragma unroll
            for (int i = 0; i < 8; i++)
#pragma unroll
                for (int j = 0; j < 8; j++) acc[i][j] += ar[i] * br[j];
        }
        __syncthreads();
    }

#pragma unroll
    for (int i = 0; i < 8; i++) {
        int row = bm + ty + i;
        if (row < M) {
            *(float4*)&g_h[(size_t)row * 128 + tx]     = make_float4(acc[i][0], acc[i][1], acc[i][2], acc[i][3]);
            *(float4*)&g_h[(size_t)row * 128 + tx + 4] = make_float4(acc[i][4], acc[i][5], acc[i][6], acc[i][7]);
        }
    }
}

// ---------------- kernel 2: attention logits, warp per node (coalesced) -----
__global__ void k_att(const float* __restrict__ att_src,
                      const float* __restrict__ att_dst, int n) {
    int gid  = blockIdx.x * blockDim.x + threadIdx.x;
    int node = gid >> 5;
    int lane = gid & 31;
    if (node >= n) return;

    float4 hv = *(const float4*)&g_h[(size_t)node * HC + lane * 4];
    float4 vs = *(const float4*)&att_src[lane * 4];   // [H*C] flat, col = lane*4
    float4 vd = *(const float4*)&att_dst[lane * 4];
    float s = hv.x * vs.x + hv.y * vs.y + hv.z * vs.z + hv.w * vs.w;
    float d = hv.x * vd.x + hv.y * vd.y + hv.z * vd.z + hv.w * vd.w;

    // reduce within each 8-lane head group
#pragma unroll
    for (int off = 4; off >= 1; off >>= 1) {
        s += __shfl_xor_sync(0xFFFFFFFFu, s, off);
        d += __shfl_xor_sync(0xFFFFFFFFu, d, off);
    }
    if ((lane & 7) == 0) {
        int h = lane >> 3;
        g_as[node * 4 + h] = s;
        g_ad[node * 4 + h] = d;
    }
}

// ---------------- kernel 3: fused softmax-weight + scatter (warp per edge) --
// ee = exp(leakyrelu(a_s[s]+a_d[d]))   (no max shift; logits are O(10))
// den[d] += ee ;  out[d] += ee * h[s]
__global__ void k_agg(const int* __restrict__ ei, int E, int n,
                      float* __restrict__ out) {
    int gid = blockIdx.x * blockDim.x + threadIdx.x;
    int e = gid >> 5;
    int lane = gid & 31;
    if (e >= E + n) return;
    int s, d;
    if (e < E) { s = ei[e]; d = ei[E + e]; }
    else       { s = d = e - E; }

    float ee = 0.0f;
    if (lane < 4) {
        float ev = g_as[s * 4 + lane] + g_ad[d * 4 + lane];
        ev = ev >= 0.f ? ev : 0.2f * ev;
        ee = __expf(ev) ;
        // use precise expf to match reference closely
        ee = expf(ev);
        atomicAdd(&g_den[d * 4 + lane], ee);
    }
    int head = lane >> 3;                       // 8 lanes per head
    float w = __shfl_sync(0xFFFFFFFFu, ee, head);
    float4 hv = *(const float4*)&g_h[(size_t)s * HC + lane * 4];
    red_add_v4(&out[(size_t)d * HC + lane * 4], hv.x * w, hv.y * w, hv.z * w, hv.w * w);
}

// ---------------- kernel 4: divide, bias, PReLU (in place) ----------------
__global__ void k_final(float* __restrict__ out, const float* __restrict__ bias,
                        const float* __restrict__ prelu_a, int n) {
    int i = blockIdx.x * blockDim.x + threadIdx.x;
    if (i >= n * HC) return;
    int node = i >> 7;
    int j = i & 127;
    int h = j >> 5;
    float den = g_den[node * 4 + h];
    float v = out[i] / fmaxf(den, 1e-16f) + bias[j];
    float a = *prelu_a;
    out[i] = v >= 0.f ? v : a * v;
}

// ---------------- launch ----------------
extern "C" void kernel_launch(void* const* d_in, const int* in_sizes, int n_in,
                              void* d_out, int out_size) {
    const float* x        = (const float*)d_in[0];
    const float* W        = (const float*)d_in[1];
    const float* att_src  = (const float*)d_in[2];
    const float* att_dst  = (const float*)d_in[3];
    const float* bias     = (const float*)d_in[4];
    const float* prelu_a  = (const float*)d_in[5];
    const int*   ei       = (const int*)d_in[6];   // int32 (JAX x64 disabled)

    const int n  = in_sizes[0] / FIN;   // 50000
    const int E  = in_sizes[6] / 2;     // 1600000
    const int ET = E + n;
    float* out = (float*)d_out;

    k_init  <<<(n * HC + 511) / 512, 512>>>(out, n * HC, n * HH);
    k_gemm  <<<(n + 127) / 128, 256>>>(x, W, n);
    k_att   <<<((long long)n * 32 + 255) / 256, 256>>>(att_src, att_dst, n);
    k_agg   <<<((long long)ET * 32 + 255) / 256, 256>>>(ei, E, n, out);
    k_final <<<(n * HC + 255) / 256, 256>>>(out, bias, prelu_a, n);
}

// round 9
// speedup vs baseline: 1.4553x; 1.2194x over previous
#include <cuda_runtime.h>
#include <cuda_bf16.h>
#include <cstdint>

#define NN   50000
#define FIN  256
#define HH   4
#define CC   32
#define HC   128
#define EMAX 1600000

// ---------------- scratch (static __device__, no allocations) ----------------
__device__ float g_h [(size_t)NN * HC];  // dropout(x) @ W  (25.6 MB)
__device__ float g_as[NN * HH];          // <h, att_src>
__device__ float g_ad[NN * HH];          // <h, att_dst>
__device__ int   g_rowptr[NN + 1];       // CSR row pointers (by dst)
__device__ int   g_cnt[NN];              // degree counters / write cursors
__device__ int   g_srcs[EMAX + NN];      // CSR: src node per incoming edge

// JAX partitionable threefry dropout factor for element index i:
// (b1,b2) = threefry2x32(key=(0,1), x0=0, x1=i); bits = b1^b2
// keep if bitcast((bits>>9)|0x3f800000)-1 < 0.8  ->  * 1.25, else 0
__device__ __forceinline__ float drop_factor(unsigned i) {
    unsigned x0 = 0u, x1 = i;
    const unsigned ks0 = 0u, ks1 = 1u, ks2 = 0x1BD11BDBu;
    x0 += ks0; x1 += ks1;
#define TF_R(r) { x0 += x1; x1 = (x1 << (r)) | (x1 >> (32 - (r))); x1 ^= x0; }
    TF_R(13) TF_R(15) TF_R(26) TF_R(6)   x0 += ks1; x1 += ks2 + 1u;
    TF_R(17) TF_R(29) TF_R(16) TF_R(24)  x0 += ks2; x1 += ks0 + 2u;
    TF_R(13) TF_R(15) TF_R(26) TF_R(6)   x0 += ks0; x1 += ks1 + 3u;
    TF_R(17) TF_R(29) TF_R(16) TF_R(24)  x0 += ks1; x1 += ks2 + 4u;
    TF_R(13) TF_R(15) TF_R(26) TF_R(6)   x0 += ks2; x1 += ks0 + 5u;
#undef TF_R
    unsigned bits = x0 ^ x1;
    float u = __uint_as_float((bits >> 9) | 0x3F800000u) - 1.0f;
    return (u < 0.8f) ? 1.25f : 0.0f;
}

// ---------------- CSR build ----------------
__global__ void k_cnt_init(int n) {
    int i = blockIdx.x * blockDim.x + threadIdx.x;
    if (i < n) g_cnt[i] = 1;             // 1 = the self-loop
}
__global__ void k_hist(const int* __restrict__ ei, int E) {
    int e = blockIdx.x * blockDim.x + threadIdx.x;
    if (e < E) atomicAdd(&g_cnt[ei[E + e]], 1);
}
// single-block inclusive-scan -> exclusive rowptr; g_cnt becomes write cursor
__global__ void k_scan(int n) {
    __shared__ int part[1024];
    const int tid = threadIdx.x;
    const int chunk = (n + 1023) / 1024;
    const int lo = tid * chunk;
    const int hi = min(lo + chunk, n);
    int sum = 0;
    for (int i = lo; i < hi; i++) sum += g_cnt[i];
    part[tid] = sum;
    __syncthreads();
    for (int off = 1; off < 1024; off <<= 1) {
        int v = 0;
        if (tid >= off) v = part[tid - off];
        __syncthreads();
        if (tid >= off) part[tid] += v;
        __syncthreads();
    }
    int run = (tid == 0) ? 0 : part[tid - 1];
    for (int i = lo; i < hi; i++) {
        int c = g_cnt[i];
        g_rowptr[i] = run;
        g_cnt[i]    = run;               // cursor for scatter
        run += c;
    }
    if (tid == 1023) g_rowptr[n] = part[1023];
}
__global__ void k_scatter(const int* __restrict__ ei, int E, int n) {
    int e = blockIdx.x * blockDim.x + threadIdx.x;
    if (e >= E + n) return;
    int s, d;
    if (e < E) { s = ei[e]; d = ei[E + e]; }
    else       { s = d = e - E; }
    int pos = atomicAdd(&g_cnt[d], 1);
    g_srcs[pos] = s;
}

// ---------------- SGEMM with fused threefry dropout on A --------------------
// h = dropout(x) @ W   (M x 256 @ 256 x 128)
__global__ void k_gemm(const float* __restrict__ X, const float* __restrict__ W, int M) {
    __shared__ float As[16][128];
    __shared__ float Bs[16][128];
    const int bm  = blockIdx.x * 128;
    const int tid = threadIdx.x;

    const int arow = tid >> 2;          // 0..63
    const int acol = (tid & 3) << 2;    // 0,4,8,12
    const int brow = tid >> 5;          // 0..7
    const int bcol = (tid & 31) << 2;   // 0..124

    const int tx = (tid & 15) << 3;     // out col base
    const int ty = (tid >> 4) << 3;     // out row base (within tile)

    float acc[8][8];
#pragma unroll
    for (int i = 0; i < 8; i++)
#pragma unroll
        for (int j = 0; j < 8; j++) acc[i][j] = 0.0f;

    for (int kt = 0; kt < 256; kt += 16) {
#pragma unroll
        for (int r = 0; r < 2; r++) {
            int row = bm + arow + r * 64;
            float4 v = make_float4(0.f, 0.f, 0.f, 0.f);
            if (row < M) {
                unsigned base = (unsigned)row * 256u + (unsigned)(kt + acol);
                v = *(const float4*)&X[(size_t)row * 256 + kt + acol];
                v.x *= drop_factor(base + 0u);
                v.y *= drop_factor(base + 1u);
                v.z *= drop_factor(base + 2u);
                v.w *= drop_factor(base + 3u);
            }
            As[acol + 0][arow + r * 64] = v.x;
            As[acol + 1][arow + r * 64] = v.y;
            As[acol + 2][arow + r * 64] = v.z;
            As[acol + 3][arow + r * 64] = v.w;
        }
#pragma unroll
        for (int r = 0; r < 2; r++) {
            *(float4*)&Bs[brow + r * 8][bcol] =
                *(const float4*)&W[(size_t)(kt + brow + r * 8) * 128 + bcol];
        }
        __syncthreads();

#pragma unroll
        for (int k = 0; k < 16; k++) {
            float4 a0 = *(float4*)&As[k][ty];
            float4 a1 = *(float4*)&As[k][ty + 4];
            float4 b0 = *(float4*)&Bs[k][tx];
            float4 b1 = *(float4*)&Bs[k][tx + 4];
            float ar[8] = {a0.x, a0.y, a0.z, a0.w, a1.x, a1.y, a1.z, a1.w};
            float br[8] = {b0.x, b0.y, b0.z, b0.w, b1.x, b1.y, b1.z, b1.w};
#pragma unroll
            for (int i = 0; i < 8; i++)
#pragma unroll
                for (int j = 0; j < 8; j++) acc[i][j] += ar[i] * br[j];
        }
        __syncthreads();
    }

#pragma unroll
    for (int i = 0; i < 8; i++) {
        int row = bm + ty + i;
        if (row < M) {
            *(float4*)&g_h[(size_t)row * 128 + tx]     = make_float4(acc[i][0], acc[i][1], acc[i][2], acc[i][3]);
            *(float4*)&g_h[(size_t)row * 128 + tx + 4] = make_float4(acc[i][4], acc[i][5], acc[i][6], acc[i][7]);
        }
    }
}

// ---------------- attention logits, warp per node (coalesced) ---------------
__global__ void k_att(const float* __restrict__ att_src,
                      const float* __restrict__ att_dst, int n) {
    int gid  = blockIdx.x * blockDim.x + threadIdx.x;
    int node = gid >> 5;
    int lane = gid & 31;
    if (node >= n) return;

    float4 hv = *(const float4*)&g_h[(size_t)node * HC + lane * 4];
    float4 vs = *(const float4*)&att_src[lane * 4];
    float4 vd = *(const float4*)&att_dst[lane * 4];
    float s = hv.x * vs.x + hv.y * vs.y + hv.z * vs.z + hv.w * vs.w;
    float d = hv.x * vd.x + hv.y * vd.y + hv.z * vd.z + hv.w * vd.w;

#pragma unroll
    for (int off = 4; off >= 1; off >>= 1) {
        s += __shfl_xor_sync(0xFFFFFFFFu, s, off);
        d += __shfl_xor_sync(0xFFFFFFFFu, d, off);
    }
    if ((lane & 7) == 0) {
        int h = lane >> 3;
        g_as[node * 4 + h] = s;
        g_ad[node * 4 + h] = d;
    }
}

// ---------------- fused aggregate + softmax-div + bias + PReLU --------------
// warp per dst node; register accumulation; no atomics; single output write.
__global__ void k_agg(const float* __restrict__ bias,
                      const float* __restrict__ prelu_a,
                      float* __restrict__ out, int n) {
    int gid  = blockIdx.x * blockDim.x + threadIdx.x;
    int node = gid >> 5;
    int lane = gid & 31;
    if (node >= n) return;

    const int start = g_rowptr[node];
    const int end   = g_rowptr[node + 1];
    const int sub   = lane >> 2;        // 0..7 : edge slot in batch
    const int hl    = lane & 3;         // head for logit compute
    const int hh    = lane >> 3;        // head of this lane's output cols

    const float adl = g_ad[node * 4 + hl];   // dst logit term for head hl

    float acc0 = 0.f, acc1 = 0.f, acc2 = 0.f, acc3 = 0.f;
    float den_p = 0.f;                  // partial denominator for head hl

    for (int j = start; j < end; j += 8) {
        int jj = j + sub;
        float ee = 0.f;
        int   sE = 0;
        if (jj < end) {
            sE = g_srcs[jj];
            float ev = g_as[sE * 4 + hl] + adl;
            ev = ev >= 0.f ? ev : 0.2f * ev;
            ee = expf(ev);
        }
        den_p += ee;
#pragma unroll
        for (int b = 0; b < 8; b++) {
            if (j + b >= end) break;
            float w = __shfl_sync(0xFFFFFFFFu, ee, b * 4 + hh);
            int   s = __shfl_sync(0xFFFFFFFFu, sE, b * 4);
            float4 hv = *(const float4*)&g_h[(size_t)s * HC + lane * 4];
            acc0 += w * hv.x; acc1 += w * hv.y; acc2 += w * hv.z; acc3 += w * hv.w;
        }
    }

    // reduce den over sub lanes (same hl): lanes {hl, hl+4, ..., hl+28}
#pragma unroll
    for (int off = 16; off >= 4; off >>= 1)
        den_p += __shfl_xor_sync(0xFFFFFFFFu, den_p, off);
    // lane hl now holds den[hl]; fetch den for this lane's output head hh
    float den = __shfl_sync(0xFFFFFFFFu, den_p, hh);
    float inv = 1.0f / fmaxf(den, 1e-16f);

    const float a = *prelu_a;
    float4 bv = *(const float4*)&bias[lane * 4];
    float4 o;
    o.x = acc0 * inv + bv.x;
    o.y = acc1 * inv + bv.y;
    o.z = acc2 * inv + bv.z;
    o.w = acc3 * inv + bv.w;
    o.x = o.x >= 0.f ? o.x : a * o.x;
    o.y = o.y >= 0.f ? o.y : a * o.y;
    o.z = o.z >= 0.f ? o.z : a * o.z;
    o.w = o.w >= 0.f ? o.w : a * o.w;
    *(float4*)&out[(size_t)node * HC + lane * 4] = o;
}

// ---------------- launch ----------------
extern "C" void kernel_launch(void* const* d_in, const int* in_sizes, int n_in,
                              void* d_out, int out_size) {
    const float* x        = (const float*)d_in[0];
    const float* W        = (const float*)d_in[1];
    const float* att_src  = (const float*)d_in[2];
    const float* att_dst  = (const float*)d_in[3];
    const float* bias     = (const float*)d_in[4];
    const float* prelu_a  = (const float*)d_in[5];
    const int*   ei       = (const int*)d_in[6];   // int32 (JAX x64 disabled)

    const int n  = in_sizes[0] / FIN;   // 50000
    const int E  = in_sizes[6] / 2;     // 1600000
    const int ET = E + n;
    float* out = (float*)d_out;

    k_cnt_init<<<(n + 511) / 512, 512>>>(n);
    k_hist    <<<(E + 255) / 256, 256>>>(ei, E);
    k_scan    <<<1, 1024>>>(n);
    k_scatter <<<(ET + 255) / 256, 256>>>(ei, E, n);
    k_gemm    <<<(n + 127) / 128, 256>>>(x, W, n);
    k_att     <<<((long long)n * 32 + 255) / 256, 256>>>(att_src, att_dst, n);
    k_agg     <<<((long long)n * 32 + 255) / 256, 256>>>(bias, prelu_a, out, n);
}

// round 10
// speedup vs baseline: 1.4835x; 1.0194x over previous
#include <cuda_runtime.h>
#include <cuda_bf16.h>
#include <cstdint>

#define NN   50000
#define FIN  256
#define HH   4
#define CC   32
#define HC   128
#define EMAX 1600000

// ---------------- scratch (static __device__, no allocations) ----------------
__device__ float g_h [(size_t)NN * HC];  // dropout(x) @ W  (25.6 MB)
__device__ float g_as[NN * HH];          // <h, att_src>
__device__ float g_ad[NN * HH];          // <h, att_dst>
__device__ int   g_rowptr[NN + 1];       // CSR row pointers (by dst)
__device__ int   g_cnt[NN];              // degree counters / write cursors
__device__ int   g_srcs[EMAX + NN];      // CSR: src node per incoming edge

// JAX partitionable threefry dropout factor for element index i:
// (b1,b2) = threefry2x32(key=(0,1), x0=0, x1=i); bits = b1^b2
// keep if bitcast((bits>>9)|0x3f800000)-1 < 0.8  ->  * 1.25, else 0
__device__ __forceinline__ float drop_factor(unsigned i) {
    unsigned x0 = 0u, x1 = i;
    const unsigned ks0 = 0u, ks1 = 1u, ks2 = 0x1BD11BDBu;
    x0 += ks0; x1 += ks1;
#define TF_R(r) { x0 += x1; x1 = (x1 << (r)) | (x1 >> (32 - (r))); x1 ^= x0; }
    TF_R(13) TF_R(15) TF_R(26) TF_R(6)   x0 += ks1; x1 += ks2 + 1u;
    TF_R(17) TF_R(29) TF_R(16) TF_R(24)  x0 += ks2; x1 += ks0 + 2u;
    TF_R(13) TF_R(15) TF_R(26) TF_R(6)   x0 += ks0; x1 += ks1 + 3u;
    TF_R(17) TF_R(29) TF_R(16) TF_R(24)  x0 += ks1; x1 += ks2 + 4u;
    TF_R(13) TF_R(15) TF_R(26) TF_R(6)   x0 += ks2; x1 += ks0 + 5u;
#undef TF_R
    unsigned bits = x0 ^ x1;
    float u = __uint_as_float((bits >> 9) | 0x3F800000u) - 1.0f;
    return (u < 0.8f) ? 1.25f : 0.0f;
}

// ---------------- CSR build ----------------
__global__ void k_cnt_init(int n) {
    int i = blockIdx.x * blockDim.x + threadIdx.x;
    if (i < n) g_cnt[i] = 1;             // 1 = the self-loop
}
__global__ void k_hist(const int* __restrict__ ei, int E) {
    int e = blockIdx.x * blockDim.x + threadIdx.x;
    if (e < E) atomicAdd(&g_cnt[ei[E + e]], 1);
}
// single-block scan -> exclusive rowptr; g_cnt becomes write cursor
__global__ void k_scan(int n) {
    __shared__ int part[1024];
    const int tid = threadIdx.x;
    const int chunk = (n + 1023) / 1024;
    const int lo = tid * chunk;
    const int hi = min(lo + chunk, n);
    int sum = 0;
    for (int i = lo; i < hi; i++) sum += g_cnt[i];
    part[tid] = sum;
    __syncthreads();
    for (int off = 1; off < 1024; off <<= 1) {
        int v = 0;
        if (tid >= off) v = part[tid - off];
        __syncthreads();
        if (tid >= off) part[tid] += v;
        __syncthreads();
    }
    int run = (tid == 0) ? 0 : part[tid - 1];
    for (int i = lo; i < hi; i++) {
        int c = g_cnt[i];
        g_rowptr[i] = run;
        g_cnt[i]    = run;               // cursor for scatter
        run += c;
    }
    if (tid == 1023) g_rowptr[n] = part[1023];
}
__global__ void k_scatter(const int* __restrict__ ei, int E, int n) {
    int e = blockIdx.x * blockDim.x + threadIdx.x;
    if (e >= E + n) return;
    int s, d;
    if (e < E) { s = ei[e]; d = ei[E + e]; }
    else       { s = d = e - E; }
    int pos = atomicAdd(&g_cnt[d], 1);
    g_srcs[pos] = s;
}

// ---------------- SGEMM: fused dropout, double-buffered, fused att logits ---
// h = dropout(x) @ W   (M x 256 @ 256 x 128); epilogue computes g_as/g_ad
__global__ void k_gemm(const float* __restrict__ X, const float* __restrict__ W,
                       const float* __restrict__ att_src,
                       const float* __restrict__ att_dst, int M) {
    __shared__ float As[2][16][128];
    __shared__ float Bs[2][16][128];
    const int bm  = blockIdx.x * 128;
    const int tid = threadIdx.x;

    const int arow = tid >> 2;          // 0..63
    const int acol = (tid & 3) << 2;    // 0,4,8,12
    const int brow = tid >> 5;          // 0..7
    const int bcol = (tid & 31) << 2;   // 0..124

    const int tx = (tid & 15) << 3;     // out col base
    const int ty = (tid >> 4) << 3;     // out row base (within tile)

    const int rowA0 = bm + arow;
    const int rowA1 = bm + arow + 64;

    float acc[8][8];
#pragma unroll
    for (int i = 0; i < 8; i++)
#pragma unroll
        for (int j = 0; j < 8; j++) acc[i][j] = 0.0f;

    float4 aN[2], bN[2];

    // prologue: load + drop + store K-chunk 0 into buffer 0
#pragma unroll
    for (int r = 0; r < 2; r++) {
        int row = r ? rowA1 : rowA0;
        aN[r] = make_float4(0.f, 0.f, 0.f, 0.f);
        if (row < M) {
            aN[r] = *(const float4*)&X[(size_t)row * 256 + acol];
            unsigned base = (unsigned)row * 256u + (unsigned)acol;
            aN[r].x *= drop_factor(base + 0u);
            aN[r].y *= drop_factor(base + 1u);
            aN[r].z *= drop_factor(base + 2u);
            aN[r].w *= drop_factor(base + 3u);
        }
        bN[r] = *(const float4*)&W[(size_t)(brow + r * 8) * 128 + bcol];
    }
#pragma unroll
    for (int r = 0; r < 2; r++) {
        As[0][acol + 0][arow + r * 64] = aN[r].x;
        As[0][acol + 1][arow + r * 64] = aN[r].y;
        As[0][acol + 2][arow + r * 64] = aN[r].z;
        As[0][acol + 3][arow + r * 64] = aN[r].w;
        *(float4*)&Bs[0][brow + r * 8][bcol] = bN[r];
    }
    __syncthreads();

    for (int kt_i = 0; kt_i < 16; kt_i++) {
        const int cur = kt_i & 1;
        if (kt_i < 15) {
            const int kt = (kt_i + 1) * 16;
#pragma unroll
            for (int r = 0; r < 2; r++) {
                int row = r ? rowA1 : rowA0;
                aN[r] = make_float4(0.f, 0.f, 0.f, 0.f);
                if (row < M) aN[r] = *(const float4*)&X[(size_t)row * 256 + kt + acol];
                bN[r] = *(const float4*)&W[(size_t)(kt + brow + r * 8) * 128 + bcol];
            }
        }

#pragma unroll
        for (int k = 0; k < 16; k++) {
            float4 a0 = *(float4*)&As[cur][k][ty];
            float4 a1 = *(float4*)&As[cur][k][ty + 4];
            float4 b0 = *(float4*)&Bs[cur][k][tx];
            float4 b1 = *(float4*)&Bs[cur][k][tx + 4];
            float ar[8] = {a0.x, a0.y, a0.z, a0.w, a1.x, a1.y, a1.z, a1.w};
            float br[8] = {b0.x, b0.y, b0.z, b0.w, b1.x, b1.y, b1.z, b1.w};
#pragma unroll
            for (int i = 0; i < 8; i++)
#pragma unroll
                for (int j = 0; j < 8; j++) acc[i][j] += ar[i] * br[j];
        }

        if (kt_i < 15) {
            const int kt = (kt_i + 1) * 16;
            const int nxt = cur ^ 1;
#pragma unroll
            for (int r = 0; r < 2; r++) {
                int row = r ? rowA1 : rowA0;
                if (row < M) {
                    unsigned base = (unsigned)row * 256u + (unsigned)(kt + acol);
                    aN[r].x *= drop_factor(base + 0u);
                    aN[r].y *= drop_factor(base + 1u);
                    aN[r].z *= drop_factor(base + 2u);
                    aN[r].w *= drop_factor(base + 3u);
                }
                As[nxt][acol + 0][arow + r * 64] = aN[r].x;
                As[nxt][acol + 1][arow + r * 64] = aN[r].y;
                As[nxt][acol + 2][arow + r * 64] = aN[r].z;
                As[nxt][acol + 3][arow + r * 64] = aN[r].w;
                *(float4*)&Bs[nxt][brow + r * 8][bcol] = bN[r];
            }
            __syncthreads();
        }
    }

    // epilogue: store h + fused attention logits
    float4 vs0 = *(const float4*)&att_src[tx];
    float4 vs1 = *(const float4*)&att_src[tx + 4];
    float4 vd0 = *(const float4*)&att_dst[tx];
    float4 vd1 = *(const float4*)&att_dst[tx + 4];
    const int lane = tid & 31;
    const int head = (lane & 15) >> 2;          // head of this thread's cols

#pragma unroll
    for (int i = 0; i < 8; i++) {
        int row = bm + ty + i;
        if (row < M) {
            *(float4*)&g_h[(size_t)row * 128 + tx]     = make_float4(acc[i][0], acc[i][1], acc[i][2], acc[i][3]);
            *(float4*)&g_h[(size_t)row * 128 + tx + 4] = make_float4(acc[i][4], acc[i][5], acc[i][6], acc[i][7]);
        }
        float s = acc[i][0] * vs0.x + acc[i][1] * vs0.y + acc[i][2] * vs0.z + acc[i][3] * vs0.w
                + acc[i][4] * vs1.x + acc[i][5] * vs1.y + acc[i][6] * vs1.z + acc[i][7] * vs1.w;
        float d = acc[i][0] * vd0.x + acc[i][1] * vd0.y + acc[i][2] * vd0.z + acc[i][3] * vd0.w
                + acc[i][4] * vd1.x + acc[i][5] * vd1.y + acc[i][6] * vd1.z + acc[i][7] * vd1.w;
        // sum the 4 threads of this head (lane offsets 1,2 within 4-lane group)
        s += __shfl_xor_sync(0xFFFFFFFFu, s, 1);
        s += __shfl_xor_sync(0xFFFFFFFFu, s, 2);
        d += __shfl_xor_sync(0xFFFFFFFFu, d, 1);
        d += __shfl_xor_sync(0xFFFFFFFFu, d, 2);
        if ((lane & 3) == 0 && row < M) {
            g_as[row * 4 + head] = s;
            g_ad[row * 4 + head] = d;
        }
    }
}

// ---------------- fused aggregate + softmax-div + bias + PReLU --------------
// warp per dst node; register accumulation; no atomics; single output write.
__global__ void k_agg(const float* __restrict__ bias,
                      const float* __restrict__ prelu_a,
                      float* __restrict__ out, int n) {
    int gid  = blockIdx.x * blockDim.x + threadIdx.x;
    int node = gid >> 5;
    int lane = gid & 31;
    if (node >= n) return;

    const int start = g_rowptr[node];
    const int end   = g_rowptr[node + 1];
    const int sub   = lane >> 2;        // 0..7 : edge slot in batch
    const int hl    = lane & 3;         // head for logit compute
    const int hh    = lane >> 3;        // head of this lane's output cols

    const float adl = g_ad[node * 4 + hl];   // dst logit term for head hl

    float acc0 = 0.f, acc1 = 0.f, acc2 = 0.f, acc3 = 0.f;
    float den_p = 0.f;                  // partial denominator for head hl

    for (int j = start; j < end; j += 8) {
        int jj = j + sub;
        float ee = 0.f;
        int   sE = 0;
        if (jj < end) {
            sE = g_srcs[jj];
            float ev = g_as[sE * 4 + hl] + adl;
            ev = ev >= 0.f ? ev : 0.2f * ev;
            ee = expf(ev);
        }
        den_p += ee;
#pragma unroll
        for (int b = 0; b < 8; b++) {
            if (j + b >= end) break;
            float w = __shfl_sync(0xFFFFFFFFu, ee, b * 4 + hh);
            int   s = __shfl_sync(0xFFFFFFFFu, sE, b * 4);
            float4 hv = *(const float4*)&g_h[(size_t)s * HC + lane * 4];
            acc0 += w * hv.x; acc1 += w * hv.y; acc2 += w * hv.z; acc3 += w * hv.w;
        }
    }

    // reduce den over sub lanes (same hl): lanes {hl, hl+4, ..., hl+28}
#pragma unroll
    for (int off = 16; off >= 4; off >>= 1)
        den_p += __shfl_xor_sync(0xFFFFFFFFu, den_p, off);
    float den = __shfl_sync(0xFFFFFFFFu, den_p, hh);
    float inv = 1.0f / fmaxf(den, 1e-16f);

    const float a = *prelu_a;
    float4 bv = *(const float4*)&bias[lane * 4];
    float4 o;
    o.x = acc0 * inv + bv.x;
    o.y = acc1 * inv + bv.y;
    o.z = acc2 * inv + bv.z;
    o.w = acc3 * inv + bv.w;
    o.x = o.x >= 0.f ? o.x : a * o.x;
    o.y = o.y >= 0.f ? o.y : a * o.y;
    o.z = o.z >= 0.f ? o.z : a * o.z;
    o.w = o.w >= 0.f ? o.w : a * o.w;
    *(float4*)&out[(size_t)node * HC + lane * 4] = o;
}

// ---------------- launch ----------------
extern "C" void kernel_launch(void* const* d_in, const int* in_sizes, int n_in,
                              void* d_out, int out_size) {
    const float* x        = (const float*)d_in[0];
    const float* W        = (const float*)d_in[1];
    const float* att_src  = (const float*)d_in[2];
    const float* att_dst  = (const float*)d_in[3];
    const float* bias     = (const float*)d_in[4];
    const float* prelu_a  = (const float*)d_in[5];
    const int*   ei       = (const int*)d_in[6];   // int32 (JAX x64 disabled)

    const int n  = in_sizes[0] / FIN;   // 50000
    const int E  = in_sizes[6] / 2;     // 1600000
    const int ET = E + n;
    float* out = (float*)d_out;

    k_cnt_init<<<(n + 511) / 512, 512>>>(n);
    k_hist    <<<(E + 255) / 256, 256>>>(ei, E);
    k_scan    <<<1, 1024>>>(n);
    k_scatter <<<(ET + 255) / 256, 256>>>(ei, E, n);
    k_gemm    <<<(n + 127) / 128, 256>>>(x, W, att_src, att_dst, n);
    k_agg     <<<((long long)n * 32 + 255) / 256, 256>>>(bias, prelu_a, out, n);
}

// round 11
// speedup vs baseline: 1.5178x; 1.0231x over previous
#include <cuda_runtime.h>
#include <cuda_bf16.h>
#include <cstdint>

#define NN   50000
#define FIN  256
#define HH   4
#define CC   32
#define HC   128
#define EMAX 1600000

// ---------------- scratch (static __device__, no allocations) ----------------
__device__ float g_h [(size_t)NN * HC];  // dropout(x) @ W  (25.6 MB)
__device__ float g_as[NN * HH];          // <h, att_src>
__device__ float g_ad[NN * HH];          // <h, att_dst>
__device__ int   g_rowptr[NN + 1];       // CSR row pointers (by dst)
__device__ int   g_cnt[NN];              // degree counters / write cursors
__device__ int   g_srcs[EMAX + NN];      // CSR: src node per incoming edge

// JAX partitionable threefry dropout factor for element index i:
// (b1,b2) = threefry2x32(key=(0,1), x0=0, x1=i); bits = b1^b2
// keep if bitcast((bits>>9)|0x3f800000)-1 < 0.8  ->  * 1.25, else 0
__device__ __forceinline__ float drop_factor(unsigned i) {
    unsigned x0 = 0u, x1 = i;
    const unsigned ks0 = 0u, ks1 = 1u, ks2 = 0x1BD11BDBu;
    x0 += ks0; x1 += ks1;
#define TF_R(r) { x0 += x1; x1 = (x1 << (r)) | (x1 >> (32 - (r))); x1 ^= x0; }
    TF_R(13) TF_R(15) TF_R(26) TF_R(6)   x0 += ks1; x1 += ks2 + 1u;
    TF_R(17) TF_R(29) TF_R(16) TF_R(24)  x0 += ks2; x1 += ks0 + 2u;
    TF_R(13) TF_R(15) TF_R(26) TF_R(6)   x0 += ks0; x1 += ks1 + 3u;
    TF_R(17) TF_R(29) TF_R(16) TF_R(24)  x0 += ks1; x1 += ks2 + 4u;
    TF_R(13) TF_R(15) TF_R(26) TF_R(6)   x0 += ks2; x1 += ks0 + 5u;
#undef TF_R
    unsigned bits = x0 ^ x1;
    float u = __uint_as_float((bits >> 9) | 0x3F800000u) - 1.0f;
    return (u < 0.8f) ? 1.25f : 0.0f;
}

// ---------------- CSR build ----------------
__global__ void k_cnt_init(int n) {
    int i = blockIdx.x * blockDim.x + threadIdx.x;
    if (i < n) g_cnt[i] = 1;             // 1 = the self-loop
}
__global__ void k_hist(const int* __restrict__ ei, int E) {
    int e = blockIdx.x * blockDim.x + threadIdx.x;
    if (e < E) atomicAdd(&g_cnt[ei[E + e]], 1);
}
// single-block scan -> exclusive rowptr; g_cnt becomes write cursor
__global__ void k_scan(int n) {
    __shared__ int part[1024];
    const int tid = threadIdx.x;
    const int chunk = (n + 1023) / 1024;
    const int lo = tid * chunk;
    const int hi = min(lo + chunk, n);
    int sum = 0;
    for (int i = lo; i < hi; i++) sum += g_cnt[i];
    part[tid] = sum;
    __syncthreads();
    for (int off = 1; off < 1024; off <<= 1) {
        int v = 0;
        if (tid >= off) v = part[tid - off];
        __syncthreads();
        if (tid >= off) part[tid] += v;
        __syncthreads();
    }
    int run = (tid == 0) ? 0 : part[tid - 1];
    for (int i = lo; i < hi; i++) {
        int c = g_cnt[i];
        g_rowptr[i] = run;
        g_cnt[i]    = run;               // cursor for scatter
        run += c;
    }
    if (tid == 1023) g_rowptr[n] = part[1023];
}
__global__ void k_scatter(const int* __restrict__ ei, int E, int n) {
    int e = blockIdx.x * blockDim.x + threadIdx.x;
    if (e >= E + n) return;
    int s, d;
    if (e < E) { s = ei[e]; d = ei[E + e]; }
    else       { s = d = e - E; }
    int pos = atomicAdd(&g_cnt[d], 1);
    g_srcs[pos] = s;
}

// ---------------- SGEMM: fused dropout, double-buffered, fused att logits ---
// h = dropout(x) @ W   (M x 256 @ 256 x 128); epilogue computes g_as/g_ad
__global__ void k_gemm(const float* __restrict__ X, const float* __restrict__ W,
                       const float* __restrict__ att_src,
                       const float* __restrict__ att_dst, int M) {
    __shared__ float As[2][16][128];
    __shared__ float Bs[2][16][128];
    const int bm  = blockIdx.x * 128;
    const int tid = threadIdx.x;

    const int arow = tid >> 2;          // 0..63
    const int acol = (tid & 3) << 2;    // 0,4,8,12
    const int brow = tid >> 5;          // 0..7
    const int bcol = (tid & 31) << 2;   // 0..124

    const int tx = (tid & 15) << 3;     // out col base
    const int ty = (tid >> 4) << 3;     // out row base (within tile)

    const int rowA0 = bm + arow;
    const int rowA1 = bm + arow + 64;

    float acc[8][8];
#pragma unroll
    for (int i = 0; i < 8; i++)
#pragma unroll
        for (int j = 0; j < 8; j++) acc[i][j] = 0.0f;

    float4 aN[2], bN[2];

#pragma unroll
    for (int r = 0; r < 2; r++) {
        int row = r ? rowA1 : rowA0;
        aN[r] = make_float4(0.f, 0.f, 0.f, 0.f);
        if (row < M) {
            aN[r] = *(const float4*)&X[(size_t)row * 256 + acol];
            unsigned base = (unsigned)row * 256u + (unsigned)acol;
            aN[r].x *= drop_factor(base + 0u);
            aN[r].y *= drop_factor(base + 1u);
            aN[r].z *= drop_factor(base + 2u);
            aN[r].w *= drop_factor(base + 3u);
        }
        bN[r] = *(const float4*)&W[(size_t)(brow + r * 8) * 128 + bcol];
    }
#pragma unroll
    for (int r = 0; r < 2; r++) {
        As[0][acol + 0][arow + r * 64] = aN[r].x;
        As[0][acol + 1][arow + r * 64] = aN[r].y;
        As[0][acol + 2][arow + r * 64] = aN[r].z;
        As[0][acol + 3][arow + r * 64] = aN[r].w;
        *(float4*)&Bs[0][brow + r * 8][bcol] = bN[r];
    }
    __syncthreads();

    for (int kt_i = 0; kt_i < 16; kt_i++) {
        const int cur = kt_i & 1;
        if (kt_i < 15) {
            const int kt = (kt_i + 1) * 16;
#pragma unroll
            for (int r = 0; r < 2; r++) {
                int row = r ? rowA1 : rowA0;
                aN[r] = make_float4(0.f, 0.f, 0.f, 0.f);
                if (row < M) aN[r] = *(const float4*)&X[(size_t)row * 256 + kt + acol];
                bN[r] = *(const float4*)&W[(size_t)(kt + brow + r * 8) * 128 + bcol];
            }
        }

#pragma unroll
        for (int k = 0; k < 16; k++) {
            float4 a0 = *(float4*)&As[cur][k][ty];
            float4 a1 = *(float4*)&As[cur][k][ty + 4];
            float4 b0 = *(float4*)&Bs[cur][k][tx];
            float4 b1 = *(float4*)&Bs[cur][k][tx + 4];
            float ar[8] = {a0.x, a0.y, a0.z, a0.w, a1.x, a1.y, a1.z, a1.w};
            float br[8] = {b0.x, b0.y, b0.z, b0.w, b1.x, b1.y, b1.z, b1.w};
#pragma unroll
            for (int i = 0; i < 8; i++)
#pragma unroll
                for (int j = 0; j < 8; j++) acc[i][j] += ar[i] * br[j];
        }

        if (kt_i < 15) {
            const int kt = (kt_i + 1) * 16;
            const int nxt = cur ^ 1;
#pragma unroll
            for (int r = 0; r < 2; r++) {
                int row = r ? rowA1 : rowA0;
                if (row < M) {
                    unsigned base = (unsigned)row * 256u + (unsigned)(kt + acol);
                    aN[r].x *= drop_factor(base + 0u);
                    aN[r].y *= drop_factor(base + 1u);
                    aN[r].z *= drop_factor(base + 2u);
                    aN[r].w *= drop_factor(base + 3u);
                }
                As[nxt][acol + 0][arow + r * 64] = aN[r].x;
                As[nxt][acol + 1][arow + r * 64] = aN[r].y;
                As[nxt][acol + 2][arow + r * 64] = aN[r].z;
                As[nxt][acol + 3][arow + r * 64] = aN[r].w;
                *(float4*)&Bs[nxt][brow + r * 8][bcol] = bN[r];
            }
            __syncthreads();
        }
    }

    // epilogue: store h + fused attention logits
    float4 vs0 = *(const float4*)&att_src[tx];
    float4 vs1 = *(const float4*)&att_src[tx + 4];
    float4 vd0 = *(const float4*)&att_dst[tx];
    float4 vd1 = *(const float4*)&att_dst[tx + 4];
    const int lane = tid & 31;
    const int head = (lane & 15) >> 2;          // head of this thread's cols

#pragma unroll
    for (int i = 0; i < 8; i++) {
        int row = bm + ty + i;
        if (row < M) {
            *(float4*)&g_h[(size_t)row * 128 + tx]     = make_float4(acc[i][0], acc[i][1], acc[i][2], acc[i][3]);
            *(float4*)&g_h[(size_t)row * 128 + tx + 4] = make_float4(acc[i][4], acc[i][5], acc[i][6], acc[i][7]);
        }
        float s = acc[i][0] * vs0.x + acc[i][1] * vs0.y + acc[i][2] * vs0.z + acc[i][3] * vs0.w
                + acc[i][4] * vs1.x + acc[i][5] * vs1.y + acc[i][6] * vs1.z + acc[i][7] * vs1.w;
        float d = acc[i][0] * vd0.x + acc[i][1] * vd0.y + acc[i][2] * vd0.z + acc[i][3] * vd0.w
                + acc[i][4] * vd1.x + acc[i][5] * vd1.y + acc[i][6] * vd1.z + acc[i][7] * vd1.w;
        s += __shfl_xor_sync(0xFFFFFFFFu, s, 1);
        s += __shfl_xor_sync(0xFFFFFFFFu, s, 2);
        d += __shfl_xor_sync(0xFFFFFFFFu, d, 1);
        d += __shfl_xor_sync(0xFFFFFFFFu, d, 2);
        if ((lane & 3) == 0 && row < M) {
            g_as[row * 4 + head] = s;
            g_ad[row * 4 + head] = d;
        }
    }
}

// ---------------- fused aggregate + softmax-div + bias + PReLU --------------
// warp per dst node; 16-edge batches, fully unrolled predicated gathers.
__global__ void k_agg(const float* __restrict__ bias,
                      const float* __restrict__ prelu_a,
                      float* __restrict__ out, int n) {
    int gid  = blockIdx.x * blockDim.x + threadIdx.x;
    int node = gid >> 5;
    int lane = gid & 31;
    if (node >= n) return;

    const int start = g_rowptr[node];
    const int end   = g_rowptr[node + 1];
    const int sub   = lane >> 2;        // 0..7 : edge slot in batch
    const int hl    = lane & 3;         // head for logit compute
    const int hh    = lane >> 3;        // head of this lane's output cols

    const float adl = g_ad[node * 4 + hl];   // dst logit term for head hl

    float acc0 = 0.f, acc1 = 0.f, acc2 = 0.f, acc3 = 0.f;
    float den_p = 0.f;                  // partial denominator for head hl

    for (int j = start; j < end; j += 16) {
        // two edge slots per lane: jj0 = j+sub, jj1 = j+8+sub
        int   jj0 = j + sub,      jj1 = j + 8 + sub;
        float ee0 = 0.f, ee1 = 0.f;
        int   sE0 = 0,   sE1 = 0;
        if (jj0 < end) {
            sE0 = g_srcs[jj0];
            float ev = g_as[sE0 * 4 + hl] + adl;
            ev = ev >= 0.f ? ev : 0.2f * ev;
            ee0 = expf(ev);
        }
        if (jj1 < end) {
            sE1 = g_srcs[jj1];
            float ev = g_as[sE1 * 4 + hl] + adl;
            ev = ev >= 0.f ? ev : 0.2f * ev;
            ee1 = expf(ev);
        }
        den_p += ee0 + ee1;

#pragma unroll
        for (int b = 0; b < 8; b++) {
            float w = __shfl_sync(0xFFFFFFFFu, ee0, b * 4 + hh);
            int   s = __shfl_sync(0xFFFFFFFFu, sE0, b * 4);
            if (j + b < end) {
                float4 hv = *(const float4*)&g_h[(size_t)s * HC + lane * 4];
                acc0 += w * hv.x; acc1 += w * hv.y; acc2 += w * hv.z; acc3 += w * hv.w;
            }
        }
#pragma unroll
        for (int b = 0; b < 8; b++) {
            float w = __shfl_sync(0xFFFFFFFFu, ee1, b * 4 + hh);
            int   s = __shfl_sync(0xFFFFFFFFu, sE1, b * 4);
            if (j + 8 + b < end) {
                float4 hv = *(const float4*)&g_h[(size_t)s * HC + lane * 4];
                acc0 += w * hv.x; acc1 += w * hv.y; acc2 += w * hv.z; acc3 += w * hv.w;
            }
        }
    }

    // reduce den over lanes with the same hl (offsets 4..16 cover all 8 subs)
#pragma unroll
    for (int off = 16; off >= 4; off >>= 1)
        den_p += __shfl_xor_sync(0xFFFFFFFFu, den_p, off);
    float den = __shfl_sync(0xFFFFFFFFu, den_p, hh);
    float inv = 1.0f / fmaxf(den, 1e-16f);

    const float a = *prelu_a;
    float4 bv = *(const float4*)&bias[lane * 4];
    float4 o;
    o.x = acc0 * inv + bv.x;
    o.y = acc1 * inv + bv.y;
    o.z = acc2 * inv + bv.z;
    o.w = acc3 * inv + bv.w;
    o.x = o.x >= 0.f ? o.x : a * o.x;
    o.y = o.y >= 0.f ? o.y : a * o.y;
    o.z = o.z >= 0.f ? o.z : a * o.z;
    o.w = o.w >= 0.f ? o.w : a * o.w;
    *(float4*)&out[(size_t)node * HC + lane * 4] = o;
}

// ---------------- launch ----------------
extern "C" void kernel_launch(void* const* d_in, const int* in_sizes, int n_in,
                              void* d_out, int out_size) {
    const float* x        = (const float*)d_in[0];
    const float* W        = (const float*)d_in[1];
    const float* att_src  = (const float*)d_in[2];
    const float* att_dst  = (const float*)d_in[3];
    const float* bias     = (const float*)d_in[4];
    const float* prelu_a  = (const float*)d_in[5];
    const int*   ei       = (const int*)d_in[6];   // int32 (JAX x64 disabled)

    const int n  = in_sizes[0] / FIN;   // 50000
    const int E  = in_sizes[6] / 2;     // 1600000
    const int ET = E + n;
    float* out = (float*)d_out;

    k_cnt_init<<<(n + 511) / 512, 512>>>(n);
    k_hist    <<<(E + 255) / 256, 256>>>(ei, E);
    k_scan    <<<1, 1024>>>(n);
    k_scatter <<<(ET + 255) / 256, 256>>>(ei, E, n);
    k_gemm    <<<(n + 127) / 128, 256>>>(x, W, att_src, att_dst, n);
    k_agg     <<<((long long)n * 32 + 255) / 256, 256>>>(bias, prelu_a, out, n);
}

// round 12
// speedup vs baseline: 1.7706x; 1.1665x over previous
#include <cuda_runtime.h>
#include <cuda_bf16.h>
#include <cstdint>

#define NN   50000
#define FIN  256
#define HH   4
#define CC   32
#define HC   128
#define EMAX 1600000

// ---------------- scratch (static __device__, no allocations) ----------------
__device__ float g_h [(size_t)NN * HC];  // dropout(x) @ W  (25.6 MB)
__device__ float g_as[NN * HH];          // <h, att_src>
__device__ float g_ad[NN * HH];          // <h, att_dst>
__device__ int   g_rowptr[NN + 1];       // CSR row pointers (by dst)
__device__ int   g_cnt[NN];              // degree counters / write cursors
__device__ int   g_srcs[EMAX + NN];      // CSR: src node per incoming edge

// JAX partitionable threefry dropout factor for element index i:
// (b1,b2) = threefry2x32(key=(0,1), x0=0, x1=i); bits = b1^b2
// keep if bitcast((bits>>9)|0x3f800000)-1 < 0.8  ->  * 1.25, else 0
__device__ __forceinline__ float drop_factor(unsigned i) {
    unsigned x0 = 0u, x1 = i;
    const unsigned ks0 = 0u, ks1 = 1u, ks2 = 0x1BD11BDBu;
    x0 += ks0; x1 += ks1;
#define TF_R(r) { x0 += x1; x1 = (x1 << (r)) | (x1 >> (32 - (r))); x1 ^= x0; }
    TF_R(13) TF_R(15) TF_R(26) TF_R(6)   x0 += ks1; x1 += ks2 + 1u;
    TF_R(17) TF_R(29) TF_R(16) TF_R(24)  x0 += ks2; x1 += ks0 + 2u;
    TF_R(13) TF_R(15) TF_R(26) TF_R(6)   x0 += ks0; x1 += ks1 + 3u;
    TF_R(17) TF_R(29) TF_R(16) TF_R(24)  x0 += ks1; x1 += ks2 + 4u;
    TF_R(13) TF_R(15) TF_R(26) TF_R(6)   x0 += ks2; x1 += ks0 + 5u;
#undef TF_R
    unsigned bits = x0 ^ x1;
    float u = __uint_as_float((bits >> 9) | 0x3F800000u) - 1.0f;
    return (u < 0.8f) ? 1.25f : 0.0f;
}

// ---------------- CSR build ----------------
__global__ void k_cnt_init(int n) {
    int i = blockIdx.x * blockDim.x + threadIdx.x;
    if (i < n) g_cnt[i] = 1;             // 1 = the self-loop
}
__global__ void k_hist(const int* __restrict__ ei, int E) {
    int e = blockIdx.x * blockDim.x + threadIdx.x;
    if (e < E) atomicAdd(&g_cnt[ei[E + e]], 1);
}
// single-block scan -> exclusive rowptr; g_cnt becomes write cursor
__global__ void k_scan(int n) {
    __shared__ int part[1024];
    const int tid = threadIdx.x;
    const int chunk = (n + 1023) / 1024;
    const int lo = tid * chunk;
    const int hi = min(lo + chunk, n);
    int sum = 0;
    for (int i = lo; i < hi; i++) sum += g_cnt[i];
    part[tid] = sum;
    __syncthreads();
    for (int off = 1; off < 1024; off <<= 1) {
        int v = 0;
        if (tid >= off) v = part[tid - off];
        __syncthreads();
        if (tid >= off) part[tid] += v;
        __syncthreads();
    }
    int run = (tid == 0) ? 0 : part[tid - 1];
    for (int i = lo; i < hi; i++) {
        int c = g_cnt[i];
        g_rowptr[i] = run;
        g_cnt[i]    = run;               // cursor for scatter
        run += c;
    }
    if (tid == 1023) g_rowptr[n] = part[1023];
}
__global__ void k_scatter(const int* __restrict__ ei, int E, int n) {
    int e = blockIdx.x * blockDim.x + threadIdx.x;
    if (e >= E + n) return;
    int s, d;
    if (e < E) { s = ei[e]; d = ei[E + e]; }
    else       { s = d = e - E; }
    int pos = atomicAdd(&g_cnt[d], 1);
    g_srcs[pos] = s;
}

// ---------------- SGEMM: fused dropout, double-buffered, fused att logits ---
// h = dropout(x) @ W   (M x 256 @ 256 x 128); epilogue computes g_as/g_ad
__global__ void k_gemm(const float* __restrict__ X, const float* __restrict__ W,
                       const float* __restrict__ att_src,
                       const float* __restrict__ att_dst, int M) {
    __shared__ float As[2][16][128];
    __shared__ float Bs[2][16][128];
    const int bm  = blockIdx.x * 128;
    const int tid = threadIdx.x;

    const int arow = tid >> 2;          // 0..63
    const int acol = (tid & 3) << 2;    // 0,4,8,12
    const int brow = tid >> 5;          // 0..7
    const int bcol = (tid & 31) << 2;   // 0..124

    const int tx = (tid & 15) << 3;     // out col base
    const int ty = (tid >> 4) << 3;     // out row base (within tile)

    const int rowA0 = bm + arow;
    const int rowA1 = bm + arow + 64;

    float acc[8][8];
#pragma unroll
    for (int i = 0; i < 8; i++)
#pragma unroll
        for (int j = 0; j < 8; j++) acc[i][j] = 0.0f;

    float4 aN[2], bN[2];

#pragma unroll
    for (int r = 0; r < 2; r++) {
        int row = r ? rowA1 : rowA0;
        aN[r] = make_float4(0.f, 0.f, 0.f, 0.f);
        if (row < M) {
            aN[r] = *(const float4*)&X[(size_t)row * 256 + acol];
            unsigned base = (unsigned)row * 256u + (unsigned)acol;
            aN[r].x *= drop_factor(base + 0u);
            aN[r].y *= drop_factor(base + 1u);
            aN[r].z *= drop_factor(base + 2u);
            aN[r].w *= drop_factor(base + 3u);
        }
        bN[r] = *(const float4*)&W[(size_t)(brow + r * 8) * 128 + bcol];
    }
#pragma unroll
    for (int r = 0; r < 2; r++) {
        As[0][acol + 0][arow + r * 64] = aN[r].x;
        As[0][acol + 1][arow + r * 64] = aN[r].y;
        As[0][acol + 2][arow + r * 64] = aN[r].z;
        As[0][acol + 3][arow + r * 64] = aN[r].w;
        *(float4*)&Bs[0][brow + r * 8][bcol] = bN[r];
    }
    __syncthreads();

    for (int kt_i = 0; kt_i < 16; kt_i++) {
        const int cur = kt_i & 1;
        if (kt_i < 15) {
            const int kt = (kt_i + 1) * 16;
#pragma unroll
            for (int r = 0; r < 2; r++) {
                int row = r ? rowA1 : rowA0;
                aN[r] = make_float4(0.f, 0.f, 0.f, 0.f);
                if (row < M) aN[r] = *(const float4*)&X[(size_t)row * 256 + kt + acol];
                bN[r] = *(const float4*)&W[(size_t)(kt + brow + r * 8) * 128 + bcol];
            }
        }

#pragma unroll
        for (int k = 0; k < 16; k++) {
            float4 a0 = *(float4*)&As[cur][k][ty];
            float4 a1 = *(float4*)&As[cur][k][ty + 4];
            float4 b0 = *(float4*)&Bs[cur][k][tx];
            float4 b1 = *(float4*)&Bs[cur][k][tx + 4];
            float ar[8] = {a0.x, a0.y, a0.z, a0.w, a1.x, a1.y, a1.z, a1.w};
            float br[8] = {b0.x, b0.y, b0.z, b0.w, b1.x, b1.y, b1.z, b1.w};
#pragma unroll
            for (int i = 0; i < 8; i++)
#pragma unroll
                for (int j = 0; j < 8; j++) acc[i][j] += ar[i] * br[j];
        }

        if (kt_i < 15) {
            const int kt = (kt_i + 1) * 16;
            const int nxt = cur ^ 1;
#pragma unroll
            for (int r = 0; r < 2; r++) {
                int row = r ? rowA1 : rowA0;
                if (row < M) {
                    unsigned base = (unsigned)row * 256u + (unsigned)(kt + acol);
                    aN[r].x *= drop_factor(base + 0u);
                    aN[r].y *= drop_factor(base + 1u);
                    aN[r].z *= drop_factor(base + 2u);
                    aN[r].w *= drop_factor(base + 3u);
                }
                As[nxt][acol + 0][arow + r * 64] = aN[r].x;
                As[nxt][acol + 1][arow + r * 64] = aN[r].y;
                As[nxt][acol + 2][arow + r * 64] = aN[r].z;
                As[nxt][acol + 3][arow + r * 64] = aN[r].w;
                *(float4*)&Bs[nxt][brow + r * 8][bcol] = bN[r];
            }
            __syncthreads();
        }
    }

    // epilogue: store h + fused attention logits
    float4 vs0 = *(const float4*)&att_src[tx];
    float4 vs1 = *(const float4*)&att_src[tx + 4];
    float4 vd0 = *(const float4*)&att_dst[tx];
    float4 vd1 = *(const float4*)&att_dst[tx + 4];
    const int lane = tid & 31;
    const int head = (lane & 15) >> 2;          // head of this thread's cols

#pragma unroll
    for (int i = 0; i < 8; i++) {
        int row = bm + ty + i;
        if (row < M) {
            *(float4*)&g_h[(size_t)row * 128 + tx]     = make_float4(acc[i][0], acc[i][1], acc[i][2], acc[i][3]);
            *(float4*)&g_h[(size_t)row * 128 + tx + 4] = make_float4(acc[i][4], acc[i][5], acc[i][6], acc[i][7]);
        }
        float s = acc[i][0] * vs0.x + acc[i][1] * vs0.y + acc[i][2] * vs0.z + acc[i][3] * vs0.w
                + acc[i][4] * vs1.x + acc[i][5] * vs1.y + acc[i][6] * vs1.z + acc[i][7] * vs1.w;
        float d = acc[i][0] * vd0.x + acc[i][1] * vd0.y + acc[i][2] * vd0.z + acc[i][3] * vd0.w
                + acc[i][4] * vd1.x + acc[i][5] * vd1.y + acc[i][6] * vd1.z + acc[i][7] * vd1.w;
        s += __shfl_xor_sync(0xFFFFFFFFu, s, 1);
        s += __shfl_xor_sync(0xFFFFFFFFu, s, 2);
        d += __shfl_xor_sync(0xFFFFFFFFu, d, 1);
        d += __shfl_xor_sync(0xFFFFFFFFu, d, 2);
        if ((lane & 3) == 0 && row < M) {
            g_as[row * 4 + head] = s;
            g_ad[row * 4 + head] = d;
        }
    }
}

// ---------------- fused aggregate + softmax-div + bias + PReLU --------------
// warp per dst node; 16-edge batches, fully unrolled predicated gathers.
__global__ void k_agg(const float* __restrict__ bias,
                      const float* __restrict__ prelu_a,
                      float* __restrict__ out, int n) {
    int gid  = blockIdx.x * blockDim.x + threadIdx.x;
    int node = gid >> 5;
    int lane = gid & 31;
    if (node >= n) return;

    const int start = g_rowptr[node];
    const int end   = g_rowptr[node + 1];
    const int sub   = lane >> 2;        // 0..7 : edge slot in batch
    const int hl    = lane & 3;         // head for logit compute
    const int hh    = lane >> 3;        // head of this lane's output cols

    const float adl = g_ad[node * 4 + hl];   // dst logit term for head hl

    float acc0 = 0.f, acc1 = 0.f, acc2 = 0.f, acc3 = 0.f;
    float den_p = 0.f;                  // partial denominator for head hl

    for (int j = start; j < end; j += 16) {
        int   jj0 = j + sub,      jj1 = j + 8 + sub;
        float ee0 = 0.f, ee1 = 0.f;
        int   sE0 = 0,   sE1 = 0;
        if (jj0 < end) {
            sE0 = g_srcs[jj0];
            float ev = g_as[sE0 * 4 + hl] + adl;
            ev = ev >= 0.f ? ev : 0.2f * ev;
            ee0 = expf(ev);
        }
        if (jj1 < end) {
            sE1 = g_srcs[jj1];
            float ev = g_as[sE1 * 4 + hl] + adl;
            ev = ev >= 0.f ? ev : 0.2f * ev;
            ee1 = expf(ev);
        }
        den_p += ee0 + ee1;

#pragma unroll
        for (int b = 0; b < 8; b++) {
            float w = __shfl_sync(0xFFFFFFFFu, ee0, b * 4 + hh);
            int   s = __shfl_sync(0xFFFFFFFFu, sE0, b * 4);
            if (j + b < end) {
                float4 hv = *(const float4*)&g_h[(size_t)s * HC + lane * 4];
                acc0 += w * hv.x; acc1 += w * hv.y; acc2 += w * hv.z; acc3 += w * hv.w;
            }
        }
#pragma unroll
        for (int b = 0; b < 8; b++) {
            float w = __shfl_sync(0xFFFFFFFFu, ee1, b * 4 + hh);
            int   s = __shfl_sync(0xFFFFFFFFu, sE1, b * 4);
            if (j + 8 + b < end) {
                float4 hv = *(const float4*)&g_h[(size_t)s * HC + lane * 4];
                acc0 += w * hv.x; acc1 += w * hv.y; acc2 += w * hv.z; acc3 += w * hv.w;
            }
        }
    }

#pragma unroll
    for (int off = 16; off >= 4; off >>= 1)
        den_p += __shfl_xor_sync(0xFFFFFFFFu, den_p, off);
    float den = __shfl_sync(0xFFFFFFFFu, den_p, hh);
    float inv = 1.0f / fmaxf(den, 1e-16f);

    const float a = *prelu_a;
    float4 bv = *(const float4*)&bias[lane * 4];
    float4 o;
    o.x = acc0 * inv + bv.x;
    o.y = acc1 * inv + bv.y;
    o.z = acc2 * inv + bv.z;
    o.w = acc3 * inv + bv.w;
    o.x = o.x >= 0.f ? o.x : a * o.x;
    o.y = o.y >= 0.f ? o.y : a * o.y;
    o.z = o.z >= 0.f ? o.z : a * o.z;
    o.w = o.w >= 0.f ? o.w : a * o.w;
    *(float4*)&out[(size_t)node * HC + lane * 4] = o;
}

// ---------------- launch (stream-forked: CSR build ∥ GEMM) ----------------
extern "C" void kernel_launch(void* const* d_in, const int* in_sizes, int n_in,
                              void* d_out, int out_size) {
    const float* x        = (const float*)d_in[0];
    const float* W        = (const float*)d_in[1];
    const float* att_src  = (const float*)d_in[2];
    const float* att_dst  = (const float*)d_in[3];
    const float* bias     = (const float*)d_in[4];
    const float* prelu_a  = (const float*)d_in[5];
    const int*   ei       = (const int*)d_in[6];   // int32 (JAX x64 disabled)

    const int n  = in_sizes[0] / FIN;   // 50000
    const int E  = in_sizes[6] / 2;     // 1600000
    const int ET = E + n;
    float* out = (float*)d_out;

    // one-time stream/event creation (first call is the uncaptured correctness run)
    static cudaStream_t s_csr = nullptr;
    static cudaEvent_t  ev_fork = nullptr, ev_join = nullptr;
    if (s_csr == nullptr) {
        cudaStreamCreateWithFlags(&s_csr, cudaStreamNonBlocking);
        cudaEventCreateWithFlags(&ev_fork, cudaEventDisableTiming);
        cudaEventCreateWithFlags(&ev_join, cudaEventDisableTiming);
    }

    // fork: CSR build on s_csr, GEMM on the main (capture) stream
    cudaEventRecord(ev_fork, 0);
    cudaStreamWaitEvent(s_csr, ev_fork, 0);

    k_cnt_init<<<(n + 511) / 512, 512, 0, s_csr>>>(n);
    k_hist    <<<(E + 255) / 256, 256, 0, s_csr>>>(ei, E);
    k_scan    <<<1, 1024, 0, s_csr>>>(n);
    k_scatter <<<(ET + 255) / 256, 256, 0, s_csr>>>(ei, E, n);
    cudaEventRecord(ev_join, s_csr);

    k_gemm    <<<(n + 127) / 128, 256>>>(x, W, att_src, att_dst, n);

    // join: agg needs both CSR and h/as/ad
    cudaStreamWaitEvent(0, ev_join, 0);
    k_agg     <<<((long long)n * 32 + 255) / 256, 256>>>(bias, prelu_a, out, n);
}